// round 1
// baseline (speedup 1.0000x reference)
#include <cuda_runtime.h>
#include <cuda_fp16.h>
#include <cstdint>
#include <cstddef>

// ---------------- problem constants ----------------
#define N_NODES 50000
#define N_EDGES 1600000
constexpr int D0 = 512, D1 = 2048, D2 = 1024, D3 = 512;

// ---------------- device scratch (statics = allowed scratch) ----------------
__device__ float  g_inv[N_NODES];
__device__ int    g_cnt[N_NODES];
__device__ int    g_rowptr[N_NODES + 1];
__device__ int    g_cursor[N_NODES];
__device__ int    g_scol[N_EDGES];
__device__ float  g_sval[N_EDGES];
__device__ __half g_t1[N_NODES * D0];        // A@h0                (fp16, GEMM1 A)
__device__ __half g_h1[N_NODES * D1];        // leaky(t1@W0+b0)     (fp16, GEMM2 A)
__device__ float  g_s2[N_NODES * D2];        // h1@W1               (fp32, SPMM2 src)
__device__ __half g_h2[N_NODES * D2];        // leaky(A@s2+b1)      (fp16, GEMM3 A)
__device__ float  g_s3[N_NODES * D3];        // h2@W2               (fp32, SPMM3 src)
__device__ __half g_W0h[D0 * D1];
__device__ __half g_W1h[D1 * D2];
__device__ __half g_W2h[D2 * D3];

// ---------------- small utility kernels ----------------
__global__ void norm_kernel(const float* __restrict__ x, float* __restrict__ inv) {
    int row = blockIdx.x, tid = threadIdx.x;               // 128 threads, 4 floats each
    const float4* x4 = reinterpret_cast<const float4*>(x);
    float4 v = x4[(size_t)row * (D0 / 4) + tid];
    float ss = v.x * v.x + v.y * v.y + v.z * v.z + v.w * v.w;
    #pragma unroll
    for (int o = 16; o; o >>= 1) ss += __shfl_xor_sync(0xffffffffu, ss, o);
    __shared__ float sw[4];
    if ((tid & 31) == 0) sw[tid >> 5] = ss;
    __syncthreads();
    if (tid == 0) {
        float t = sw[0] + sw[1] + sw[2] + sw[3];
        inv[row] = 1.0f / fmaxf(sqrtf(t), 1e-12f);
    }
}

__global__ void zero_int_kernel(int* __restrict__ p, int n) {
    for (int i = blockIdx.x * blockDim.x + threadIdx.x; i < n; i += gridDim.x * blockDim.x)
        p[i] = 0;
}

__global__ void count_kernel(const int* __restrict__ erow, int* __restrict__ cnt, int E) {
    for (int i = blockIdx.x * blockDim.x + threadIdx.x; i < E; i += gridDim.x * blockDim.x)
        atomicAdd(&cnt[erow[i]], 1);
}

__global__ void scan_kernel(const int* __restrict__ cnt, int* __restrict__ rowptr) {
    __shared__ int sh[1024];
    __shared__ int carry;
    int t = threadIdx.x;
    if (t == 0) { carry = 0; rowptr[0] = 0; }
    __syncthreads();
    for (int base = 0; base < N_NODES; base += 1024) {
        int i = base + t;
        int v = (i < N_NODES) ? cnt[i] : 0;
        sh[t] = v;
        __syncthreads();
        #pragma unroll
        for (int off = 1; off < 1024; off <<= 1) {
            int u = (t >= off) ? sh[t - off] : 0;
            __syncthreads();
            sh[t] += u;
            __syncthreads();
        }
        if (i < N_NODES) rowptr[i + 1] = carry + sh[t];
        __syncthreads();
        if (t == 0) carry += sh[1023];
        __syncthreads();
    }
}

__global__ void copy_int_kernel(const int* __restrict__ src, int* __restrict__ dst, int n) {
    for (int i = blockIdx.x * blockDim.x + threadIdx.x; i < n; i += gridDim.x * blockDim.x)
        dst[i] = src[i];
}

__global__ void scatter_kernel(const int* __restrict__ erow, const int* __restrict__ ecol,
                               const float* __restrict__ eval, int* __restrict__ cursor,
                               int* __restrict__ scol, float* __restrict__ sval, int E) {
    for (int i = blockIdx.x * blockDim.x + threadIdx.x; i < E; i += gridDim.x * blockDim.x) {
        int r = erow[i];
        int p = atomicAdd(&cursor[r], 1);
        scol[p] = ecol[i];
        sval[p] = eval[i];
    }
}

__global__ void f2h_kernel(const float* __restrict__ in, __half* __restrict__ out, int n) {
    for (int i = blockIdx.x * blockDim.x + threadIdx.x; i < n; i += gridDim.x * blockDim.x)
        out[i] = __float2half_rn(in[i]);
}

// ---------------- SPMM: out[row] = sum_e val*src[col[e]]  (+bias, +leaky) ----------------
template <int D, bool SCALE, bool BIAS, bool LEAKY, typename OutT>
__global__ void spmm_kernel(const int* __restrict__ rowptr, const int* __restrict__ cols,
                            const float* __restrict__ vals, const float* __restrict__ src,
                            const float* __restrict__ inv, const float* __restrict__ bias,
                            OutT* __restrict__ out) {
    const int row = blockIdx.x;
    const int tid = threadIdx.x;                      // blockDim = D/4
    int s = __ldg(&rowptr[row]), e = __ldg(&rowptr[row + 1]);
    float ax = 0.f, ay = 0.f, az = 0.f, aw = 0.f;
    const float4* src4 = reinterpret_cast<const float4*>(src);
    #pragma unroll 4
    for (int i = s; i < e; ++i) {
        int c = __ldg(&cols[i]);
        float v = __ldg(&vals[i]);
        if (SCALE) v *= __ldg(&inv[c]);
        float4 hv = __ldg(&src4[(size_t)c * (D / 4) + tid]);
        ax = fmaf(v, hv.x, ax);
        ay = fmaf(v, hv.y, ay);
        az = fmaf(v, hv.z, az);
        aw = fmaf(v, hv.w, aw);
    }
    if (BIAS) {
        float4 b = __ldg(&reinterpret_cast<const float4*>(bias)[tid]);
        ax += b.x; ay += b.y; az += b.z; aw += b.w;
    }
    if (LEAKY) {
        ax = ax >= 0.f ? ax : 0.2f * ax;
        ay = ay >= 0.f ? ay : 0.2f * ay;
        az = az >= 0.f ? az : 0.2f * az;
        aw = aw >= 0.f ? aw : 0.2f * aw;
    }
    if constexpr (sizeof(OutT) == 2) {
        __half2* o2 = reinterpret_cast<__half2*>(out) + (size_t)row * (D / 2) + tid * 2;
        o2[0] = __floats2half2_rn(ax, ay);
        o2[1] = __floats2half2_rn(az, aw);
    } else {
        reinterpret_cast<float4*>(out)[(size_t)row * (D / 4) + tid] =
            make_float4(ax, ay, az, aw);
    }
}

// ---------------- fp16 tensor-core GEMM (mma.sync m16n8k16, fp32 accum) ----------------
#define BM 128
#define BN 128
#define BKK 32
#define LDA_S 40
#define LDB_S 136

__device__ __forceinline__ void cp16(uint32_t s, const void* g, int pbytes) {
    asm volatile("cp.async.cg.shared.global [%0], [%1], 16, %2;\n" ::"r"(s), "l"(g), "r"(pbytes));
}
__device__ __forceinline__ void ldsm_x4(uint32_t* r, uint32_t addr) {
    asm volatile("ldmatrix.sync.aligned.m8n8.x4.shared.b16 {%0,%1,%2,%3}, [%4];"
                 : "=r"(r[0]), "=r"(r[1]), "=r"(r[2]), "=r"(r[3]) : "r"(addr));
}
__device__ __forceinline__ void ldsm_x4_t(uint32_t* r, uint32_t addr) {
    asm volatile("ldmatrix.sync.aligned.m8n8.x4.trans.shared.b16 {%0,%1,%2,%3}, [%4];"
                 : "=r"(r[0]), "=r"(r[1]), "=r"(r[2]), "=r"(r[3]) : "r"(addr));
}
__device__ __forceinline__ void mma16816(float* c, const uint32_t* a, uint32_t b0, uint32_t b1) {
    asm volatile(
        "mma.sync.aligned.m16n8k16.row.col.f32.f16.f16.f32 "
        "{%0,%1,%2,%3}, {%4,%5,%6,%7}, {%8,%9}, {%0,%1,%2,%3};"
        : "+f"(c[0]), "+f"(c[1]), "+f"(c[2]), "+f"(c[3])
        : "r"(a[0]), "r"(a[1]), "r"(a[2]), "r"(a[3]), "r"(b0), "r"(b1));
}

template <typename OutT, bool FUSE>
__global__ void __launch_bounds__(256) gemm_kernel(
    const __half* __restrict__ A, const __half* __restrict__ B, OutT* __restrict__ C,
    const float* __restrict__ bias, int M, int N, int K) {
    __shared__ __half sA[2][BM * LDA_S];
    __shared__ __half sB[2][BKK * LDB_S];
    const int tid = threadIdx.x, lane = tid & 31, wid = tid >> 5;
    const int rowBase = blockIdx.y * BM, colBase = blockIdx.x * BN;
    const int wm = (wid >> 1) * 32, wn = (wid & 1) * 64;

    const uint32_t sAa = (uint32_t)__cvta_generic_to_shared(&sA[0][0]);
    const uint32_t sBa = (uint32_t)__cvta_generic_to_shared(&sB[0][0]);
    const uint32_t sAsz = BM * LDA_S * 2, sBsz = BKK * LDB_S * 2;

    auto load_tiles = [&](int stage, int k0) {
        #pragma unroll
        for (int i = 0; i < 2; i++) {               // A: 128x32 halves
            int c = tid + i * 256;
            int r = c >> 2, cw = c & 3;
            int gr = rowBase + r;
            const __half* gp = A + (size_t)min(gr, M - 1) * K + k0 + cw * 8;
            cp16(sAa + stage * sAsz + (r * LDA_S + cw * 8) * 2, gp, (gr < M) ? 16 : 0);
        }
        #pragma unroll
        for (int i = 0; i < 2; i++) {               // B: 32x128 halves
            int c = tid + i * 256;
            int r = c >> 4, cw = c & 15;
            const __half* gp = B + (size_t)(k0 + r) * N + colBase + cw * 8;
            cp16(sBa + stage * sBsz + (r * LDB_S + cw * 8) * 2, gp, 16);
        }
        asm volatile("cp.async.commit_group;\n");
    };

    float acc[2][8][4];
    #pragma unroll
    for (int a = 0; a < 2; a++)
        #pragma unroll
        for (int b = 0; b < 8; b++)
            #pragma unroll
            for (int c = 0; c < 4; c++) acc[a][b][c] = 0.f;

    load_tiles(0, 0);
    const int KT = K / BKK;
    const int aRowL = lane & 15, aColL = (lane >> 4) << 3;
    const int bRowL = (lane & 7) + ((lane >> 3) & 1) * 8, bColL = (lane >> 4) << 3;

    for (int kt = 0; kt < KT; ++kt) {
        asm volatile("cp.async.wait_group 0;\n");
        __syncthreads();
        int cur = kt & 1;
        if (kt + 1 < KT) load_tiles(cur ^ 1, (kt + 1) * BKK);
        uint32_t aB = sAa + cur * sAsz, bB = sBa + cur * sBsz;
        #pragma unroll
        for (int ks = 0; ks < 2; ++ks) {
            int k0 = ks * 16;
            uint32_t af[2][4], bf[4][4];
            #pragma unroll
            for (int mt = 0; mt < 2; ++mt)
                ldsm_x4(af[mt], aB + ((wm + mt * 16 + aRowL) * LDA_S + k0 + aColL) * 2);
            #pragma unroll
            for (int np = 0; np < 4; ++np)
                ldsm_x4_t(bf[np], bB + ((k0 + bRowL) * LDB_S + wn + np * 16 + bColL) * 2);
            #pragma unroll
            for (int mt = 0; mt < 2; ++mt)
                #pragma unroll
                for (int nt = 0; nt < 8; ++nt)
                    mma16816(acc[mt][nt], af[mt], bf[nt >> 1][(nt & 1) * 2],
                             bf[nt >> 1][(nt & 1) * 2 + 1]);
        }
    }

    // epilogue
    const int g = lane >> 2, cp2 = (lane & 3) * 2;
    #pragma unroll
    for (int mt = 0; mt < 2; ++mt) {
        #pragma unroll
        for (int nt = 0; nt < 8; ++nt) {
            int col = colBase + wn + nt * 8 + cp2;
            #pragma unroll
            for (int h = 0; h < 2; ++h) {
                int r = rowBase + wm + mt * 16 + g + h * 8;
                if (r < M) {
                    float v0 = acc[mt][nt][h * 2 + 0];
                    float v1 = acc[mt][nt][h * 2 + 1];
                    if (FUSE) {
                        v0 += __ldg(&bias[col]);
                        v1 += __ldg(&bias[col + 1]);
                        v0 = v0 >= 0.f ? v0 : 0.2f * v0;
                        v1 = v1 >= 0.f ? v1 : 0.2f * v1;
                    }
                    if constexpr (sizeof(OutT) == 2) {
                        *reinterpret_cast<__half2*>(&C[(size_t)r * N + col]) =
                            __floats2half2_rn(v0, v1);
                    } else {
                        *reinterpret_cast<float2*>(&C[(size_t)r * N + col]) =
                            make_float2(v0, v1);
                    }
                }
            }
        }
    }
}

// ---------------- launch ----------------
extern "C" void kernel_launch(void* const* d_in, const int* in_sizes, int n_in,
                              void* d_out, int out_size) {
    const float* x    = (const float*)d_in[0];
    const int*   erow = (const int*)d_in[1];
    const int*   ecol = (const int*)d_in[2];
    const float* eval = (const float*)d_in[3];
    const float* W0 = (const float*)d_in[4];
    const float* b0 = (const float*)d_in[5];
    const float* W1 = (const float*)d_in[6];
    const float* b1 = (const float*)d_in[7];
    const float* W2 = (const float*)d_in[8];
    const float* b2 = (const float*)d_in[9];
    const int E = in_sizes[1];

    float *inv, *sval, *s2, *s3;
    int *cnt, *rowptr, *cursor, *scol;
    __half *t1, *h1, *h2, *W0h, *W1h, *W2h;
    cudaGetSymbolAddress((void**)&inv, g_inv);
    cudaGetSymbolAddress((void**)&cnt, g_cnt);
    cudaGetSymbolAddress((void**)&rowptr, g_rowptr);
    cudaGetSymbolAddress((void**)&cursor, g_cursor);
    cudaGetSymbolAddress((void**)&scol, g_scol);
    cudaGetSymbolAddress((void**)&sval, g_sval);
    cudaGetSymbolAddress((void**)&t1, g_t1);
    cudaGetSymbolAddress((void**)&h1, g_h1);
    cudaGetSymbolAddress((void**)&s2, g_s2);
    cudaGetSymbolAddress((void**)&h2, g_h2);
    cudaGetSymbolAddress((void**)&s3, g_s3);
    cudaGetSymbolAddress((void**)&W0h, g_W0h);
    cudaGetSymbolAddress((void**)&W1h, g_W1h);
    cudaGetSymbolAddress((void**)&W2h, g_W2h);

    // weight conversions (independent, launch early)
    f2h_kernel<<<512, 256>>>(W0, W0h, D0 * D1);
    f2h_kernel<<<512, 256>>>(W1, W1h, D1 * D2);
    f2h_kernel<<<512, 256>>>(W2, W2h, D2 * D3);

    // row norms
    norm_kernel<<<N_NODES, 128>>>(x, inv);

    // CSR build
    zero_int_kernel<<<256, 256>>>(cnt, N_NODES);
    count_kernel<<<(E + 255) / 256, 256>>>(erow, cnt, E);
    scan_kernel<<<1, 1024>>>(cnt, rowptr);
    copy_int_kernel<<<256, 256>>>(rowptr, cursor, N_NODES);
    scatter_kernel<<<(E + 255) / 256, 256>>>(erow, ecol, eval, cursor, scol, sval, E);

    // layer 1: t1 = A @ (x * inv)    [spmm at d=512, before the GEMM]
    spmm_kernel<D0, true, false, false, __half>
        <<<N_NODES, D0 / 4>>>(rowptr, scol, sval, x, inv, nullptr, t1);
    // h1 = leaky(t1 @ W0 + b0)
    gemm_kernel<__half, true>
        <<<dim3(D1 / BN, (N_NODES + BM - 1) / BM), 256>>>(t1, W0h, h1, b0, N_NODES, D1, D0);

    // layer 2: s2 = h1 @ W1 ; h2 = leaky(A@s2 + b1)
    gemm_kernel<float, false>
        <<<dim3(D2 / BN, (N_NODES + BM - 1) / BM), 256>>>(h1, W1h, s2, nullptr, N_NODES, D2, D1);
    spmm_kernel<D2, false, true, true, __half>
        <<<N_NODES, D2 / 4>>>(rowptr, scol, sval, s2, nullptr, b1, h2);

    // layer 3: s3 = h2 @ W2 ; out = A@s3 + b2
    gemm_kernel<float, false>
        <<<dim3(D3 / BN, (N_NODES + BM - 1) / BM), 256>>>(h2, W2h, s3, nullptr, N_NODES, D3, D2);
    spmm_kernel<D3, false, true, false, float>
        <<<N_NODES, D3 / 4>>>(rowptr, scol, sval, s3, nullptr, b2, (float*)d_out);
}

// round 2
// speedup vs baseline: 1.3096x; 1.3096x over previous
#include <cuda_runtime.h>
#include <cuda_fp16.h>
#include <cstdint>
#include <cstddef>

// ---------------- problem constants ----------------
#define N_NODES 50000
#define N_EDGES 1600000
constexpr int D0 = 512, D1 = 2048, D2 = 1024, D3 = 512;

// ---------------- device scratch ----------------
__device__ int    g_cnt[N_NODES];
__device__ int    g_rowptr[N_NODES + 1];
__device__ int    g_cursor[N_NODES];
__device__ int    g_scol[N_EDGES];
__device__ float  g_sval[N_EDGES];
__device__ __half g_xh[N_NODES * D0];        // normalized x          (fp16, SPMM1 src)
__device__ __half g_t1[N_NODES * D0];        // A@xh                  (fp16, GEMM1 A)
__device__ __half g_h1[N_NODES * D1];        // leaky(t1@W0+b0)       (fp16, GEMM2 A)
__device__ __half g_s2[N_NODES * D2];        // h1@W1                 (fp16, SPMM2 src)
__device__ __half g_h2[N_NODES * D2];        // leaky(A@s2+b1)        (fp16, GEMM3 A)
__device__ __half g_s3[N_NODES * D3];        // h2@W2                 (fp16, SPMM3 src)
__device__ __half g_W0h[D0 * D1];
__device__ __half g_W1h[D1 * D2];
__device__ __half g_W2h[D2 * D3];

// ---------------- normalize + fp16 convert (fused) ----------------
__global__ void normh_kernel(const float* __restrict__ x, __half* __restrict__ xh) {
    int row = blockIdx.x, tid = threadIdx.x;               // 128 threads, 4 floats each
    const float4* x4 = reinterpret_cast<const float4*>(x);
    float4 v = x4[(size_t)row * (D0 / 4) + tid];
    float ss = v.x * v.x + v.y * v.y + v.z * v.z + v.w * v.w;
    #pragma unroll
    for (int o = 16; o; o >>= 1) ss += __shfl_xor_sync(0xffffffffu, ss, o);
    __shared__ float sw[4];
    __shared__ float s_inv;
    if ((tid & 31) == 0) sw[tid >> 5] = ss;
    __syncthreads();
    if (tid == 0) {
        float t = sw[0] + sw[1] + sw[2] + sw[3];
        s_inv = 1.0f / fmaxf(sqrtf(t), 1e-12f);
    }
    __syncthreads();
    float inv = s_inv;
    __half2* o2 = reinterpret_cast<__half2*>(xh) + (size_t)row * (D0 / 2) + tid * 2;
    o2[0] = __floats2half2_rn(v.x * inv, v.y * inv);
    o2[1] = __floats2half2_rn(v.z * inv, v.w * inv);
}

// ---------------- CSR build kernels ----------------
__global__ void zero_int_kernel(int* __restrict__ p, int n) {
    for (int i = blockIdx.x * blockDim.x + threadIdx.x; i < n; i += gridDim.x * blockDim.x)
        p[i] = 0;
}

__global__ void count_kernel(const int* __restrict__ erow, int* __restrict__ cnt, int E) {
    for (int i = blockIdx.x * blockDim.x + threadIdx.x; i < E; i += gridDim.x * blockDim.x)
        atomicAdd(&cnt[erow[i]], 1);
}

__global__ void scan_kernel(const int* __restrict__ cnt, int* __restrict__ rowptr) {
    __shared__ int sh[1024];
    __shared__ int carry;
    int t = threadIdx.x;
    if (t == 0) { carry = 0; rowptr[0] = 0; }
    __syncthreads();
    for (int base = 0; base < N_NODES; base += 1024) {
        int i = base + t;
        int v = (i < N_NODES) ? cnt[i] : 0;
        sh[t] = v;
        __syncthreads();
        #pragma unroll
        for (int off = 1; off < 1024; off <<= 1) {
            int u = (t >= off) ? sh[t - off] : 0;
            __syncthreads();
            sh[t] += u;
            __syncthreads();
        }
        if (i < N_NODES) rowptr[i + 1] = carry + sh[t];
        __syncthreads();
        if (t == 0) carry += sh[1023];
        __syncthreads();
    }
}

__global__ void copy_int_kernel(const int* __restrict__ src, int* __restrict__ dst, int n) {
    for (int i = blockIdx.x * blockDim.x + threadIdx.x; i < n; i += gridDim.x * blockDim.x)
        dst[i] = src[i];
}

__global__ void scatter_kernel(const int* __restrict__ erow, const int* __restrict__ ecol,
                               const float* __restrict__ eval, int* __restrict__ cursor,
                               int* __restrict__ scol, float* __restrict__ sval, int E) {
    for (int i = blockIdx.x * blockDim.x + threadIdx.x; i < E; i += gridDim.x * blockDim.x) {
        int r = erow[i];
        int p = atomicAdd(&cursor[r], 1);
        scol[p] = ecol[i];
        sval[p] = eval[i];
    }
}

__global__ void f2h_kernel(const float* __restrict__ in, __half* __restrict__ out, int n) {
    for (int i = blockIdx.x * blockDim.x + threadIdx.x; i < n; i += gridDim.x * blockDim.x)
        out[i] = __float2half_rn(in[i]);
}

// ---------------- SPMM (fp16 src): out[row] = sum_e val*src[col[e]]  (+bias,+leaky) ----------------
// blockDim = D/8, each thread owns 8 contiguous halves (one uint4 gather per edge)
template <int D, bool BIAS, bool LEAKY, typename OutT>
__global__ void spmm_h_kernel(const int* __restrict__ rowptr, const int* __restrict__ cols,
                              const float* __restrict__ vals, const __half* __restrict__ src,
                              const float* __restrict__ bias, OutT* __restrict__ out) {
    const int row = blockIdx.x;
    const int tid = threadIdx.x;
    int s = __ldg(&rowptr[row]), e = __ldg(&rowptr[row + 1]);
    float acc[8];
    #pragma unroll
    for (int j = 0; j < 8; j++) acc[j] = 0.f;
    const uint4* src8 = reinterpret_cast<const uint4*>(src);
    #pragma unroll 4
    for (int i = s; i < e; ++i) {
        int c = __ldg(&cols[i]);
        float v = __ldg(&vals[i]);
        uint4 hv = __ldg(&src8[(size_t)c * (D / 8) + tid]);
        float2 f0 = __half22float2(*reinterpret_cast<__half2*>(&hv.x));
        float2 f1 = __half22float2(*reinterpret_cast<__half2*>(&hv.y));
        float2 f2 = __half22float2(*reinterpret_cast<__half2*>(&hv.z));
        float2 f3 = __half22float2(*reinterpret_cast<__half2*>(&hv.w));
        acc[0] = fmaf(v, f0.x, acc[0]);
        acc[1] = fmaf(v, f0.y, acc[1]);
        acc[2] = fmaf(v, f1.x, acc[2]);
        acc[3] = fmaf(v, f1.y, acc[3]);
        acc[4] = fmaf(v, f2.x, acc[4]);
        acc[5] = fmaf(v, f2.y, acc[5]);
        acc[6] = fmaf(v, f3.x, acc[6]);
        acc[7] = fmaf(v, f3.y, acc[7]);
    }
    if (BIAS) {
        const float4* b4 = reinterpret_cast<const float4*>(bias);
        float4 ba = __ldg(&b4[tid * 2]);
        float4 bb = __ldg(&b4[tid * 2 + 1]);
        acc[0] += ba.x; acc[1] += ba.y; acc[2] += ba.z; acc[3] += ba.w;
        acc[4] += bb.x; acc[5] += bb.y; acc[6] += bb.z; acc[7] += bb.w;
    }
    if (LEAKY) {
        #pragma unroll
        for (int j = 0; j < 8; j++) acc[j] = acc[j] >= 0.f ? acc[j] : 0.2f * acc[j];
    }
    if constexpr (sizeof(OutT) == 2) {
        uint4 pk;
        __half2 p0 = __floats2half2_rn(acc[0], acc[1]);
        __half2 p1 = __floats2half2_rn(acc[2], acc[3]);
        __half2 p2 = __floats2half2_rn(acc[4], acc[5]);
        __half2 p3 = __floats2half2_rn(acc[6], acc[7]);
        pk.x = *reinterpret_cast<uint32_t*>(&p0);
        pk.y = *reinterpret_cast<uint32_t*>(&p1);
        pk.z = *reinterpret_cast<uint32_t*>(&p2);
        pk.w = *reinterpret_cast<uint32_t*>(&p3);
        reinterpret_cast<uint4*>(out)[(size_t)row * (D / 8) + tid] = pk;
    } else {
        float4* o4 = reinterpret_cast<float4*>(out) + (size_t)row * (D / 4) + tid * 2;
        o4[0] = make_float4(acc[0], acc[1], acc[2], acc[3]);
        o4[1] = make_float4(acc[4], acc[5], acc[6], acc[7]);
    }
}

// ---------------- fp16 tensor-core GEMM (mma.sync m16n8k16, fp32 accum) ----------------
#define BM 128
#define BN 128
#define BKK 32
#define LDA_S 40
#define LDB_S 136

__device__ __forceinline__ void cp16(uint32_t s, const void* g, int pbytes) {
    asm volatile("cp.async.cg.shared.global [%0], [%1], 16, %2;\n" ::"r"(s), "l"(g), "r"(pbytes));
}
__device__ __forceinline__ void ldsm_x4(uint32_t* r, uint32_t addr) {
    asm volatile("ldmatrix.sync.aligned.m8n8.x4.shared.b16 {%0,%1,%2,%3}, [%4];"
                 : "=r"(r[0]), "=r"(r[1]), "=r"(r[2]), "=r"(r[3]) : "r"(addr));
}
__device__ __forceinline__ void ldsm_x4_t(uint32_t* r, uint32_t addr) {
    asm volatile("ldmatrix.sync.aligned.m8n8.x4.trans.shared.b16 {%0,%1,%2,%3}, [%4];"
                 : "=r"(r[0]), "=r"(r[1]), "=r"(r[2]), "=r"(r[3]) : "r"(addr));
}
__device__ __forceinline__ void mma16816(float* c, const uint32_t* a, uint32_t b0, uint32_t b1) {
    asm volatile(
        "mma.sync.aligned.m16n8k16.row.col.f32.f16.f16.f32 "
        "{%0,%1,%2,%3}, {%4,%5,%6,%7}, {%8,%9}, {%0,%1,%2,%3};"
        : "+f"(c[0]), "+f"(c[1]), "+f"(c[2]), "+f"(c[3])
        : "r"(a[0]), "r"(a[1]), "r"(a[2]), "r"(a[3]), "r"(b0), "r"(b1));
}

template <typename OutT, bool FUSE>
__global__ void __launch_bounds__(256) gemm_kernel(
    const __half* __restrict__ A, const __half* __restrict__ B, OutT* __restrict__ C,
    const float* __restrict__ bias, int M, int N, int K) {
    __shared__ __half sA[2][BM * LDA_S];
    __shared__ __half sB[2][BKK * LDB_S];
    const int tid = threadIdx.x, lane = tid & 31, wid = tid >> 5;
    const int rowBase = blockIdx.y * BM, colBase = blockIdx.x * BN;
    const int wm = (wid >> 1) * 32, wn = (wid & 1) * 64;

    const uint32_t sAa = (uint32_t)__cvta_generic_to_shared(&sA[0][0]);
    const uint32_t sBa = (uint32_t)__cvta_generic_to_shared(&sB[0][0]);
    const uint32_t sAsz = BM * LDA_S * 2, sBsz = BKK * LDB_S * 2;

    auto load_tiles = [&](int stage, int k0) {
        #pragma unroll
        for (int i = 0; i < 2; i++) {               // A: 128x32 halves
            int c = tid + i * 256;
            int r = c >> 2, cw = c & 3;
            int gr = rowBase + r;
            const __half* gp = A + (size_t)min(gr, M - 1) * K + k0 + cw * 8;
            cp16(sAa + stage * sAsz + (r * LDA_S + cw * 8) * 2, gp, (gr < M) ? 16 : 0);
        }
        #pragma unroll
        for (int i = 0; i < 2; i++) {               // B: 32x128 halves
            int c = tid + i * 256;
            int r = c >> 4, cw = c & 15;
            const __half* gp = B + (size_t)(k0 + r) * N + colBase + cw * 8;
            cp16(sBa + stage * sBsz + (r * LDB_S + cw * 8) * 2, gp, 16);
        }
        asm volatile("cp.async.commit_group;\n");
    };

    float acc[2][8][4];
    #pragma unroll
    for (int a = 0; a < 2; a++)
        #pragma unroll
        for (int b = 0; b < 8; b++)
            #pragma unroll
            for (int c = 0; c < 4; c++) acc[a][b][c] = 0.f;

    load_tiles(0, 0);
    const int KT = K / BKK;
    const int aRowL = lane & 15, aColL = (lane >> 4) << 3;
    const int bRowL = (lane & 7) + ((lane >> 3) & 1) * 8, bColL = (lane >> 4) << 3;

    for (int kt = 0; kt < KT; ++kt) {
        asm volatile("cp.async.wait_group 0;\n");
        __syncthreads();
        int cur = kt & 1;
        if (kt + 1 < KT) load_tiles(cur ^ 1, (kt + 1) * BKK);
        uint32_t aB = sAa + cur * sAsz, bB = sBa + cur * sBsz;
        #pragma unroll
        for (int ks = 0; ks < 2; ++ks) {
            int k0 = ks * 16;
            uint32_t af[2][4], bf[4][4];
            #pragma unroll
            for (int mt = 0; mt < 2; ++mt)
                ldsm_x4(af[mt], aB + ((wm + mt * 16 + aRowL) * LDA_S + k0 + aColL) * 2);
            #pragma unroll
            for (int np = 0; np < 4; ++np)
                ldsm_x4_t(bf[np], bB + ((k0 + bRowL) * LDB_S + wn + np * 16 + bColL) * 2);
            #pragma unroll
            for (int mt = 0; mt < 2; ++mt)
                #pragma unroll
                for (int nt = 0; nt < 8; ++nt)
                    mma16816(acc[mt][nt], af[mt], bf[nt >> 1][(nt & 1) * 2],
                             bf[nt >> 1][(nt & 1) * 2 + 1]);
        }
    }

    // epilogue
    const int g = lane >> 2, cp2 = (lane & 3) * 2;
    #pragma unroll
    for (int mt = 0; mt < 2; ++mt) {
        #pragma unroll
        for (int nt = 0; nt < 8; ++nt) {
            int col = colBase + wn + nt * 8 + cp2;
            #pragma unroll
            for (int h = 0; h < 2; ++h) {
                int r = rowBase + wm + mt * 16 + g + h * 8;
                if (r < M) {
                    float v0 = acc[mt][nt][h * 2 + 0];
                    float v1 = acc[mt][nt][h * 2 + 1];
                    if (FUSE) {
                        v0 += __ldg(&bias[col]);
                        v1 += __ldg(&bias[col + 1]);
                        v0 = v0 >= 0.f ? v0 : 0.2f * v0;
                        v1 = v1 >= 0.f ? v1 : 0.2f * v1;
                    }
                    if constexpr (sizeof(OutT) == 2) {
                        *reinterpret_cast<__half2*>(&C[(size_t)r * N + col]) =
                            __floats2half2_rn(v0, v1);
                    } else {
                        *reinterpret_cast<float2*>(&C[(size_t)r * N + col]) =
                            make_float2(v0, v1);
                    }
                }
            }
        }
    }
}

// ---------------- launch ----------------
extern "C" void kernel_launch(void* const* d_in, const int* in_sizes, int n_in,
                              void* d_out, int out_size) {
    const float* x    = (const float*)d_in[0];
    const int*   erow = (const int*)d_in[1];
    const int*   ecol = (const int*)d_in[2];
    const float* eval = (const float*)d_in[3];
    const float* W0 = (const float*)d_in[4];
    const float* b0 = (const float*)d_in[5];
    const float* W1 = (const float*)d_in[6];
    const float* b1 = (const float*)d_in[7];
    const float* W2 = (const float*)d_in[8];
    const float* b2 = (const float*)d_in[9];
    const int E = in_sizes[1];

    float *sval;
    int *cnt, *rowptr, *cursor, *scol;
    __half *xh, *t1, *h1, *s2, *h2, *s3, *W0h, *W1h, *W2h;
    cudaGetSymbolAddress((void**)&cnt, g_cnt);
    cudaGetSymbolAddress((void**)&rowptr, g_rowptr);
    cudaGetSymbolAddress((void**)&cursor, g_cursor);
    cudaGetSymbolAddress((void**)&scol, g_scol);
    cudaGetSymbolAddress((void**)&sval, g_sval);
    cudaGetSymbolAddress((void**)&xh, g_xh);
    cudaGetSymbolAddress((void**)&t1, g_t1);
    cudaGetSymbolAddress((void**)&h1, g_h1);
    cudaGetSymbolAddress((void**)&s2, g_s2);
    cudaGetSymbolAddress((void**)&h2, g_h2);
    cudaGetSymbolAddress((void**)&s3, g_s3);
    cudaGetSymbolAddress((void**)&W0h, g_W0h);
    cudaGetSymbolAddress((void**)&W1h, g_W1h);
    cudaGetSymbolAddress((void**)&W2h, g_W2h);

    // weight conversions (independent, launch early)
    f2h_kernel<<<512, 256>>>(W0, W0h, D0 * D1);
    f2h_kernel<<<512, 256>>>(W1, W1h, D1 * D2);
    f2h_kernel<<<512, 256>>>(W2, W2h, D2 * D3);

    // normalized fp16 x
    normh_kernel<<<N_NODES, 128>>>(x, xh);

    // CSR build
    zero_int_kernel<<<256, 256>>>(cnt, N_NODES);
    count_kernel<<<(E + 255) / 256, 256>>>(erow, cnt, E);
    scan_kernel<<<1, 1024>>>(cnt, rowptr);
    copy_int_kernel<<<256, 256>>>(rowptr, cursor, N_NODES);
    scatter_kernel<<<(E + 255) / 256, 256>>>(erow, ecol, eval, cursor, scol, sval, E);

    // layer 1: t1 = A @ xh   [spmm at d=512 before the GEMM]
    spmm_h_kernel<D0, false, false, __half>
        <<<N_NODES, D0 / 8>>>(rowptr, scol, sval, xh, nullptr, t1);
    // h1 = leaky(t1 @ W0 + b0)
    gemm_kernel<__half, true>
        <<<dim3(D1 / BN, (N_NODES + BM - 1) / BM), 256>>>(t1, W0h, h1, b0, N_NODES, D1, D0);

    // layer 2: s2 = h1 @ W1 (fp16) ; h2 = leaky(A@s2 + b1)
    gemm_kernel<__half, false>
        <<<dim3(D2 / BN, (N_NODES + BM - 1) / BM), 256>>>(h1, W1h, s2, nullptr, N_NODES, D2, D1);
    spmm_h_kernel<D2, true, true, __half>
        <<<N_NODES, D2 / 8>>>(rowptr, scol, sval, s2, b1, h2);

    // layer 3: s3 = h2 @ W2 (fp16) ; out = A@s3 + b2
    gemm_kernel<__half, false>
        <<<dim3(D3 / BN, (N_NODES + BM - 1) / BM), 256>>>(h2, W2h, s3, nullptr, N_NODES, D3, D2);
    spmm_h_kernel<D3, true, false, float>
        <<<N_NODES, D3 / 8>>>(rowptr, scol, sval, s3, b2, (float*)d_out);
}

// round 6
// speedup vs baseline: 1.3693x; 1.0456x over previous
#include <cuda_runtime.h>
#include <cuda_fp16.h>
#include <cstdint>
#include <cstddef>

// ---------------- problem constants ----------------
#define N_NODES 50000
#define N_EDGES 1600000
constexpr int D0 = 512, D1 = 2048, D2 = 1024, D3 = 512;

// ---------------- device scratch ----------------
__device__ int    g_cnt[N_NODES];
__device__ int    g_rowptr[N_NODES + 1];
__device__ int    g_cursor[N_NODES];
__device__ int    g_scol[N_EDGES];
__device__ float  g_sval[N_EDGES];
__device__ __half g_xh[N_NODES * D0];        // normalized x          (fp16, SPMM1 src)
__device__ __half g_t1[N_NODES * D0];        // A@xh                  (fp16, GEMM1 A)
__device__ __half g_h1[(size_t)N_NODES * D1];// leaky(t1@W0+b0)       (fp16, GEMM2 A)
__device__ __half g_s2[N_NODES * D2];        // h1@W1                 (fp16, SPMM2 src)
__device__ __half g_h2[N_NODES * D2];        // leaky(A@s2+b1)        (fp16, GEMM3 A)
__device__ __half g_s3[N_NODES * D3];        // h2@W2                 (fp16, SPMM3 src)
__device__ __half g_W0h[D0 * D1];
__device__ __half g_W1h[D1 * D2];
__device__ __half g_W2h[D2 * D3];

// ---------------- normalize + fp16 convert + zero cnt (fused) ----------------
__global__ void normh_kernel(const float* __restrict__ x, __half* __restrict__ xh,
                             int* __restrict__ cnt) {
    int row = blockIdx.x, tid = threadIdx.x;               // 128 threads, 4 floats each
    if (tid == 0) cnt[row] = 0;
    const float4* x4 = reinterpret_cast<const float4*>(x);
    float4 v = x4[(size_t)row * (D0 / 4) + tid];
    float ss = v.x * v.x + v.y * v.y + v.z * v.z + v.w * v.w;
    #pragma unroll
    for (int o = 16; o; o >>= 1) ss += __shfl_xor_sync(0xffffffffu, ss, o);
    __shared__ float sw[4];
    __shared__ float s_inv;
    if ((tid & 31) == 0) sw[tid >> 5] = ss;
    __syncthreads();
    if (tid == 0) {
        float t = sw[0] + sw[1] + sw[2] + sw[3];
        s_inv = 1.0f / fmaxf(sqrtf(t), 1e-12f);
    }
    __syncthreads();
    float inv = s_inv;
    __half2* o2 = reinterpret_cast<__half2*>(xh) + (size_t)row * (D0 / 2) + tid * 2;
    o2[0] = __floats2half2_rn(v.x * inv, v.y * inv);
    o2[1] = __floats2half2_rn(v.z * inv, v.w * inv);
}

// ---------------- CSR build (count fused with W0 f2h) ----------------
__global__ void count_kernel(const int* __restrict__ erow, int* __restrict__ cnt, int E,
                             const float* __restrict__ W, __half* __restrict__ Wh, int nW) {
    int stride = gridDim.x * blockDim.x;
    for (int i = blockIdx.x * blockDim.x + threadIdx.x; i < E; i += stride)
        atomicAdd(&cnt[erow[i]], 1);
    for (int i = blockIdx.x * blockDim.x + threadIdx.x; i < nW; i += stride)
        Wh[i] = __float2half_rn(W[i]);
}

__global__ void scan_kernel(const int* __restrict__ cnt, int* __restrict__ rowptr,
                            int* __restrict__ cursor) {
    __shared__ int sh[1024];
    __shared__ int carry;
    int t = threadIdx.x;
    if (t == 0) { carry = 0; rowptr[0] = 0; cursor[0] = 0; }
    __syncthreads();
    for (int base = 0; base < N_NODES; base += 1024) {
        int i = base + t;
        int v = (i < N_NODES) ? cnt[i] : 0;
        sh[t] = v;
        __syncthreads();
        #pragma unroll
        for (int off = 1; off < 1024; off <<= 1) {
            int u = (t >= off) ? sh[t - off] : 0;
            __syncthreads();
            sh[t] += u;
            __syncthreads();
        }
        if (i < N_NODES) {
            int val = carry + sh[t];
            rowptr[i + 1] = val;
            if (i + 1 < N_NODES) cursor[i + 1] = val;
        }
        __syncthreads();
        if (t == 0) carry += sh[1023];
        __syncthreads();
    }
}

__global__ void scatter_kernel(const int* __restrict__ erow, const int* __restrict__ ecol,
                               const float* __restrict__ eval, int* __restrict__ cursor,
                               int* __restrict__ scol, float* __restrict__ sval, int E) {
    for (int i = blockIdx.x * blockDim.x + threadIdx.x; i < E; i += gridDim.x * blockDim.x) {
        int r = erow[i];
        int p = atomicAdd(&cursor[r], 1);
        scol[p] = ecol[i];
        sval[p] = eval[i];
    }
}

__global__ void f2h_kernel(const float* __restrict__ in, __half* __restrict__ out, int n) {
    for (int i = blockIdx.x * blockDim.x + threadIdx.x; i < n; i += gridDim.x * blockDim.x)
        out[i] = __float2half_rn(in[i]);
}

// ---------------- SPMM (fp16 src): out[row] = sum_e val*src[col[e]]  (+bias,+leaky) ----------------
template <int D, bool BIAS, bool LEAKY, typename OutT>
__global__ void spmm_h_kernel(const int* __restrict__ rowptr, const int* __restrict__ cols,
                              const float* __restrict__ vals, const __half* __restrict__ src,
                              const float* __restrict__ bias, OutT* __restrict__ out) {
    const int row = blockIdx.x;
    const int tid = threadIdx.x;
    int s = __ldg(&rowptr[row]), e = __ldg(&rowptr[row + 1]);
    float acc[8];
    #pragma unroll
    for (int j = 0; j < 8; j++) acc[j] = 0.f;
    const uint4* src8 = reinterpret_cast<const uint4*>(src);
    #pragma unroll 4
    for (int i = s; i < e; ++i) {
        int c = __ldg(&cols[i]);
        float v = __ldg(&vals[i]);
        uint4 hv = __ldg(&src8[(size_t)c * (D / 8) + tid]);
        float2 f0 = __half22float2(*reinterpret_cast<__half2*>(&hv.x));
        float2 f1 = __half22float2(*reinterpret_cast<__half2*>(&hv.y));
        float2 f2 = __half22float2(*reinterpret_cast<__half2*>(&hv.z));
        float2 f3 = __half22float2(*reinterpret_cast<__half2*>(&hv.w));
        acc[0] = fmaf(v, f0.x, acc[0]); acc[1] = fmaf(v, f0.y, acc[1]);
        acc[2] = fmaf(v, f1.x, acc[2]); acc[3] = fmaf(v, f1.y, acc[3]);
        acc[4] = fmaf(v, f2.x, acc[4]); acc[5] = fmaf(v, f2.y, acc[5]);
        acc[6] = fmaf(v, f3.x, acc[6]); acc[7] = fmaf(v, f3.y, acc[7]);
    }
    if (BIAS) {
        const float4* b4 = reinterpret_cast<const float4*>(bias);
        float4 ba = __ldg(&b4[tid * 2]);
        float4 bb = __ldg(&b4[tid * 2 + 1]);
        acc[0] += ba.x; acc[1] += ba.y; acc[2] += ba.z; acc[3] += ba.w;
        acc[4] += bb.x; acc[5] += bb.y; acc[6] += bb.z; acc[7] += bb.w;
    }
    if (LEAKY) {
        #pragma unroll
        for (int j = 0; j < 8; j++) acc[j] = acc[j] >= 0.f ? acc[j] : 0.2f * acc[j];
    }
    if constexpr (sizeof(OutT) == 2) {
        uint4 pk;
        __half2 p0 = __floats2half2_rn(acc[0], acc[1]);
        __half2 p1 = __floats2half2_rn(acc[2], acc[3]);
        __half2 p2 = __floats2half2_rn(acc[4], acc[5]);
        __half2 p3 = __floats2half2_rn(acc[6], acc[7]);
        pk.x = *reinterpret_cast<uint32_t*>(&p0);
        pk.y = *reinterpret_cast<uint32_t*>(&p1);
        pk.z = *reinterpret_cast<uint32_t*>(&p2);
        pk.w = *reinterpret_cast<uint32_t*>(&p3);
        reinterpret_cast<uint4*>(out)[(size_t)row * (D / 8) + tid] = pk;
    } else {
        float4* o4 = reinterpret_cast<float4*>(out) + (size_t)row * (D / 4) + tid * 2;
        o4[0] = make_float4(acc[0], acc[1], acc[2], acc[3]);
        o4[1] = make_float4(acc[4], acc[5], acc[6], acc[7]);
    }
}

// ---------------- fp16 tensor-core GEMM (mma.sync m16n8k16, fp32 accum, 3-stage) ----------------
#define BM 128
#define BN 128
#define BKK 32
#define LDA_S 40
#define LDB_S 136
constexpr int STG_A_BYTES = BM * LDA_S * 2;          // 10240
constexpr int STG_B_BYTES = BKK * LDB_S * 2;         // 8704
constexpr int STG_BYTES = STG_A_BYTES + STG_B_BYTES; // 18944
constexpr int GEMM_SMEM = 3 * STG_BYTES;             // 56832

__device__ __forceinline__ void cp16(uint32_t s, const void* g, int pbytes) {
    asm volatile("cp.async.cg.shared.global [%0], [%1], 16, %2;\n" ::"r"(s), "l"(g), "r"(pbytes));
}
__device__ __forceinline__ void ldsm_x4(uint32_t* r, uint32_t addr) {
    asm volatile("ldmatrix.sync.aligned.m8n8.x4.shared.b16 {%0,%1,%2,%3}, [%4];"
                 : "=r"(r[0]), "=r"(r[1]), "=r"(r[2]), "=r"(r[3]) : "r"(addr));
}
__device__ __forceinline__ void ldsm_x4_t(uint32_t* r, uint32_t addr) {
    asm volatile("ldmatrix.sync.aligned.m8n8.x4.trans.shared.b16 {%0,%1,%2,%3}, [%4];"
                 : "=r"(r[0]), "=r"(r[1]), "=r"(r[2]), "=r"(r[3]) : "r"(addr));
}
__device__ __forceinline__ void mma16816(float* c, const uint32_t* a, uint32_t b0, uint32_t b1) {
    asm volatile(
        "mma.sync.aligned.m16n8k16.row.col.f32.f16.f16.f32 "
        "{%0,%1,%2,%3}, {%4,%5,%6,%7}, {%8,%9}, {%0,%1,%2,%3};"
        : "+f"(c[0]), "+f"(c[1]), "+f"(c[2]), "+f"(c[3])
        : "r"(a[0]), "r"(a[1]), "r"(a[2]), "r"(a[3]), "r"(b0), "r"(b1));
}

template <typename OutT, bool FUSE>
__global__ void __launch_bounds__(256, 2) gemm_kernel(
    const __half* __restrict__ A, const __half* __restrict__ B, OutT* __restrict__ C,
    const float* __restrict__ bias, int M, int N, int K) {
    extern __shared__ __align__(128) char dsm[];
    const int tid = threadIdx.x, lane = tid & 31, wid = tid >> 5;
    const int rowBase = blockIdx.y * BM, colBase = blockIdx.x * BN;
    const int wm = (wid >> 1) * 32, wn = (wid & 1) * 64;

    const uint32_t sbase = (uint32_t)__cvta_generic_to_shared(dsm);

    auto load_tiles = [&](int stage, int k0) {
        uint32_t sAa = sbase + stage * STG_BYTES;
        uint32_t sBa = sAa + STG_A_BYTES;
        #pragma unroll
        for (int i = 0; i < 2; i++) {               // A: 128x32 halves
            int c = tid + i * 256;
            int r = c >> 2, cw = c & 3;
            int gr = rowBase + r;
            const __half* gp = A + (size_t)min(gr, M - 1) * K + k0 + cw * 8;
            cp16(sAa + (r * LDA_S + cw * 8) * 2, gp, (gr < M) ? 16 : 0);
        }
        #pragma unroll
        for (int i = 0; i < 2; i++) {               // B: 32x128 halves
            int c = tid + i * 256;
            int r = c >> 4, cw = c & 15;
            const __half* gp = B + (size_t)(k0 + r) * N + colBase + cw * 8;
            cp16(sBa + (r * LDB_S + cw * 8) * 2, gp, 16);
        }
        asm volatile("cp.async.commit_group;\n");
    };

    float acc[2][8][4];
    #pragma unroll
    for (int a = 0; a < 2; a++)
        #pragma unroll
        for (int b = 0; b < 8; b++)
            #pragma unroll
            for (int c = 0; c < 4; c++) acc[a][b][c] = 0.f;

    const int KT = K / BKK;
    load_tiles(0, 0);
    if (KT > 1) load_tiles(1, BKK);
    const int aRowL = lane & 15, aColL = (lane >> 4) << 3;
    const int bRowL = (lane & 7) + ((lane >> 3) & 1) * 8, bColL = (lane >> 4) << 3;

    int st = 0;
    for (int kt = 0; kt < KT; ++kt) {
        if (kt < KT - 1) {
            asm volatile("cp.async.wait_group 1;\n");
        } else {
            asm volatile("cp.async.wait_group 0;\n");
        }
        __syncthreads();
        if (kt + 2 < KT) {
            int ns = st + 2; if (ns >= 3) ns -= 3;
            load_tiles(ns, (kt + 2) * BKK);
        }
        uint32_t aB = sbase + st * STG_BYTES, bB = aB + STG_A_BYTES;
        #pragma unroll
        for (int ks = 0; ks < 2; ++ks) {
            int k0 = ks * 16;
            uint32_t af[2][4], bf[4][4];
            #pragma unroll
            for (int mt = 0; mt < 2; ++mt)
                ldsm_x4(af[mt], aB + ((wm + mt * 16 + aRowL) * LDA_S + k0 + aColL) * 2);
            #pragma unroll
            for (int np = 0; np < 4; ++np)
                ldsm_x4_t(bf[np], bB + ((k0 + bRowL) * LDB_S + wn + np * 16 + bColL) * 2);
            #pragma unroll
            for (int mt = 0; mt < 2; ++mt)
                #pragma unroll
                for (int nt = 0; nt < 8; ++nt)
                    mma16816(acc[mt][nt], af[mt], bf[nt >> 1][(nt & 1) * 2],
                             bf[nt >> 1][(nt & 1) * 2 + 1]);
        }
        ++st; if (st == 3) st = 0;
    }

    // epilogue
    const int g = lane >> 2, cp2 = (lane & 3) * 2;
    #pragma unroll
    for (int mt = 0; mt < 2; ++mt) {
        #pragma unroll
        for (int nt = 0; nt < 8; ++nt) {
            int col = colBase + wn + nt * 8 + cp2;
            #pragma unroll
            for (int h = 0; h < 2; ++h) {
                int r = rowBase + wm + mt * 16 + g + h * 8;
                if (r < M) {
                    float v0 = acc[mt][nt][h * 2 + 0];
                    float v1 = acc[mt][nt][h * 2 + 1];
                    if (FUSE) {
                        v0 += __ldg(&bias[col]);
                        v1 += __ldg(&bias[col + 1]);
                        v0 = v0 >= 0.f ? v0 : 0.2f * v0;
                        v1 = v1 >= 0.f ? v1 : 0.2f * v1;
                    }
                    if constexpr (sizeof(OutT) == 2) {
                        *reinterpret_cast<__half2*>(&C[(size_t)r * N + col]) =
                            __floats2half2_rn(v0, v1);
                    } else {
                        *reinterpret_cast<float2*>(&C[(size_t)r * N + col]) =
                            make_float2(v0, v1);
                    }
                }
            }
        }
    }
}

// ---------------- launch ----------------
extern "C" void kernel_launch(void* const* d_in, const int* in_sizes, int n_in,
                              void* d_out, int out_size) {
    const float* x    = (const float*)d_in[0];
    const int*   erow = (const int*)d_in[1];
    const int*   ecol = (const int*)d_in[2];
    const float* eval = (const float*)d_in[3];
    const float* W0 = (const float*)d_in[4];
    const float* b0 = (const float*)d_in[5];
    const float* W1 = (const float*)d_in[6];
    const float* b1 = (const float*)d_in[7];
    const float* W2 = (const float*)d_in[8];
    const float* b2 = (const float*)d_in[9];
    const int E = in_sizes[1];

    float* sval;
    int *cnt, *rowptr, *cursor, *scol;
    __half *xh, *t1, *h1, *s2, *h2, *s3, *W0h, *W1h, *W2h;
    cudaGetSymbolAddress((void**)&cnt, g_cnt);
    cudaGetSymbolAddress((void**)&rowptr, g_rowptr);
    cudaGetSymbolAddress((void**)&cursor, g_cursor);
    cudaGetSymbolAddress((void**)&scol, g_scol);
    cudaGetSymbolAddress((void**)&sval, g_sval);
    cudaGetSymbolAddress((void**)&xh, g_xh);
    cudaGetSymbolAddress((void**)&t1, g_t1);
    cudaGetSymbolAddress((void**)&h1, g_h1);
    cudaGetSymbolAddress((void**)&s2, g_s2);
    cudaGetSymbolAddress((void**)&h2, g_h2);
    cudaGetSymbolAddress((void**)&s3, g_s3);
    cudaGetSymbolAddress((void**)&W0h, g_W0h);
    cudaGetSymbolAddress((void**)&W1h, g_W1h);
    cudaGetSymbolAddress((void**)&W2h, g_W2h);

    cudaFuncSetAttribute(gemm_kernel<__half, true>,
                         cudaFuncAttributeMaxDynamicSharedMemorySize, GEMM_SMEM);
    cudaFuncSetAttribute(gemm_kernel<__half, false>,
                         cudaFuncAttributeMaxDynamicSharedMemorySize, GEMM_SMEM);

    // 1: normalize + fp16 x + zero cnt
    normh_kernel<<<N_NODES, 128>>>(x, xh, cnt);
    // 2: degree count + W0 f2h
    count_kernel<<<(E + 255) / 256, 256>>>(erow, cnt, E, W0, W0h, D0 * D1);
    // 3: scan (+cursor init)
    scan_kernel<<<1, 1024>>>(cnt, rowptr, cursor);
    // 4: scatter  (<- profiled slot)
    scatter_kernel<<<(E + 255) / 256, 256>>>(erow, ecol, eval, cursor, scol, sval, E);

    // layer 1: t1 = A @ xh   [spmm at d=512 before the GEMM]
    spmm_h_kernel<D0, false, false, __half>
        <<<N_NODES, D0 / 8>>>(rowptr, scol, sval, xh, nullptr, t1);
    // h1 = leaky(t1 @ W0 + b0)
    gemm_kernel<__half, true>
        <<<dim3(D1 / BN, (N_NODES + BM - 1) / BM), 256, GEMM_SMEM>>>(t1, W0h, h1, b0, N_NODES, D1, D0);

    // remaining weight conversions (off the critical front)
    f2h_kernel<<<512, 256>>>(W1, W1h, D1 * D2);
    f2h_kernel<<<512, 256>>>(W2, W2h, D2 * D3);

    // layer 2: s2 = h1 @ W1 (fp16) ; h2 = leaky(A@s2 + b1)
    gemm_kernel<__half, false>
        <<<dim3(D2 / BN, (N_NODES + BM - 1) / BM), 256, GEMM_SMEM>>>(h1, W1h, s2, nullptr, N_NODES, D2, D1);
    spmm_h_kernel<D2, true, true, __half>
        <<<N_NODES, D2 / 8>>>(rowptr, scol, sval, s2, b1, h2);

    // layer 3: s3 = h2 @ W2 (fp16) ; out = A@s3 + b2
    gemm_kernel<__half, false>
        <<<dim3(D3 / BN, (N_NODES + BM - 1) / BM), 256, GEMM_SMEM>>>(h2, W2h, s3, nullptr, N_NODES, D3, D2);
    spmm_h_kernel<D3, true, false, float>
        <<<N_NODES, D3 / 8>>>(rowptr, scol, sval, s3, b2, (float*)d_out);
}